// round 3
// baseline (speedup 1.0000x reference)
#include <cuda_runtime.h>
#include <math.h>

#define CB_K   1024
#define CH     128
#define NVEC   65536
#define QELEMS 8388608
#define NBLK   1024   // NVEC / 64
#define KT     128    // codes per k-tile
#define NKT    (CB_K / KT)   // 8 tiles

// Persistent scratch (no allocations allowed)
__device__ float g_cbT[CB_K * CH];   // tile-major transposed codebook:
                                     // tile t: [c][k_local] contiguous 16384 floats
__device__ float g_c2[CB_K];         // ||codebook[k]||^2
__device__ float g_partial[NBLK];    // per-block loss partial sums

// ---------------- packed fp32x2 helpers (FFMA2 path ptxas won't emit) -------
__device__ __forceinline__ unsigned long long ffma2(unsigned long long a,
                                                    unsigned long long b,
                                                    unsigned long long c) {
    unsigned long long d;
    asm("fma.rn.f32x2 %0, %1, %2, %3;" : "=l"(d) : "l"(a), "l"(b), "l"(c));
    return d;
}
__device__ __forceinline__ unsigned long long splat2(float x) {
    unsigned long long d;
    asm("mov.b64 %0, {%1, %1};" : "=l"(d) : "f"(x));
    return d;
}
__device__ __forceinline__ void unpack2(unsigned long long v, float& lo, float& hi) {
    asm("mov.b64 {%0, %1}, %2;" : "=f"(lo), "=f"(hi) : "l"(v));
}
__device__ __forceinline__ void cp_async16(void* smem_dst, const void* gsrc) {
    unsigned sa = (unsigned)__cvta_generic_to_shared(smem_dst);
    asm volatile("cp.async.cg.shared.global [%0], [%1], 16;" :: "r"(sa), "l"(gsrc));
}

// ---------------------------------------------------------------------------
// Prep: transpose codebook into tile-major [tile][c][k_local] + row norms^2.
// ---------------------------------------------------------------------------
__global__ void prep_kernel(const float* __restrict__ codebook) {
    int k = blockIdx.x;
    int c = threadIdx.x;
    float v = codebook[k * CH + c];
    g_cbT[(k >> 7) * (CH * KT) + c * KT + (k & 127)] = v;
    float s = v * v;
    #pragma unroll
    for (int off = 16; off > 0; off >>= 1)
        s += __shfl_down_sync(0xffffffffu, s, off);
    __shared__ float ws[4];
    if ((c & 31) == 0) ws[c >> 5] = s;
    __syncthreads();
    if (c == 0) g_c2[k] = (ws[0] + ws[1]) + (ws[2] + ws[3]);
}

// ---------------------------------------------------------------------------
// SMEM layout (floats):
//   [0      .. 8192 )  zsT[c][w]   (128 x 64)
//   [8192   .. 9216 )  c2all[1024]
//   [9216   .. 9280 )  rn2[64]
//   [9280   .. 9344 )  z2s[64]
//   [9344   .. 9360 )  redsum[16]
//   [9360   .. 9424 )  sidx[64] (ints)
//   [9472   .. 25856)  buf0 (128 c x 128 codes)
//   [25856  .. 42240)  buf1
// qr[64][129] reuses buf0 after the GEMM loop.
// ---------------------------------------------------------------------------
#define OFF_ZST   0
#define OFF_C2    8192
#define OFF_RN2   9216
#define OFF_Z2    9280
#define OFF_RED   9344
#define OFF_SIDX  9360
#define OFF_BUF0  9472
#define OFF_BUF1  25856
#define SMEM_FLOATS 42240

__global__ void __launch_bounds__(256, 1)
vq_main(const float* __restrict__ x, const float* __restrict__ codebook,
        float* __restrict__ out) {
    extern __shared__ float sf[];

    const int tid = threadIdx.x;
    const int n0  = blockIdx.x * 64;
    const int b   = n0 >> 12;          // n = b*4096 + h*64 + w
    const int h   = (n0 >> 6) & 63;
    const float* xbase = x + (size_t)b * (CH * 4096) + h * 64;

    // ---- kick off prefetch of codebook tile 0 (64KB) ----
    {
        const float4* src = reinterpret_cast<const float4*>(g_cbT);
        float4* dst = reinterpret_cast<float4*>(sf + OFF_BUF0);
        #pragma unroll
        for (int it = 0; it < 16; ++it)
            cp_async16(dst + it * 256 + tid, src + it * 256 + tid);
        asm volatile("cp.async.commit_group;");
    }

    // ---- load + transpose x tile (coalesced along w) ----
    {
        const int w  = tid & 63;
        const int c0 = tid >> 6;
        #pragma unroll
        for (int it = 0; it < 32; ++it) {
            int c = it * 4 + c0;
            sf[OFF_ZST + c * 64 + w] = xbase[c * 4096 + w];
        }
    }
    // ---- preload all c2 ----
    #pragma unroll
    for (int i = 0; i < 4; ++i)
        sf[OFF_C2 + i * 256 + tid] = g_c2[i * 256 + tid];
    __syncthreads();

    // ---- per-vector norms (64 threads, conflict-free column reads) ----
    if (tid < 64) {
        float s0 = 0.f, s1 = 0.f, s2 = 0.f, s3 = 0.f;
        #pragma unroll
        for (int c = 0; c < 128; c += 4) {
            float v0 = sf[OFF_ZST + (c + 0) * 64 + tid];
            float v1 = sf[OFF_ZST + (c + 1) * 64 + tid];
            float v2 = sf[OFF_ZST + (c + 2) * 64 + tid];
            float v3 = sf[OFF_ZST + (c + 3) * 64 + tid];
            s0 = fmaf(v0, v0, s0); s1 = fmaf(v1, v1, s1);
            s2 = fmaf(v2, v2, s2); s3 = fmaf(v3, v3, s3);
        }
        float s   = (s0 + s1) + (s2 + s3);
        float nrm = sqrtf(s);
        float r   = 1.0f / fmaxf(nrm, 1e-12f);
        sf[OFF_RN2 + tid] = 2.0f * r;
        sf[OFF_Z2  + tid] = s * r * r;
    }

    const int vg = tid >> 4;   // 0..15 : vectors 4*vg .. 4*vg+3
    const int cg = tid & 15;   // 0..15 : float4 chunks {cg, cg+16} of the 128-code tile

    float bestE[4];
    int   bestI[4];
    #pragma unroll
    for (int i = 0; i < 4; ++i) { bestE[i] = 3.4e38f; bestI[i] = 0; }

    const float4* zp = reinterpret_cast<const float4*>(sf + OFF_ZST);

    for (int kt = 0; kt < NKT; ++kt) {
        // prefetch next tile into the other buffer (prev compute on it is done:
        // we synced at the end of the previous iteration)
        if (kt + 1 < NKT) {
            const float4* src = reinterpret_cast<const float4*>(
                g_cbT + (kt + 1) * (CH * KT));
            float4* dst = reinterpret_cast<float4*>(
                sf + (((kt + 1) & 1) ? OFF_BUF1 : OFF_BUF0));
            #pragma unroll
            for (int it = 0; it < 16; ++it)
                cp_async16(dst + it * 256 + tid, src + it * 256 + tid);
            asm volatile("cp.async.commit_group;");
            asm volatile("cp.async.wait_group 1;");
        } else {
            asm volatile("cp.async.wait_group 0;");
        }
        __syncthreads();   // tile kt fully visible to all threads

        const float* bufb = sf + ((kt & 1) ? OFF_BUF1 : OFF_BUF0);
        const ulonglong2* cbu = reinterpret_cast<const ulonglong2*>(bufb);

        unsigned long long acc[4][4];   // [vec][code-pair]; pairs: chunk cg (2), chunk cg+16 (2)
        #pragma unroll
        for (int i = 0; i < 4; ++i)
            #pragma unroll
            for (int j = 0; j < 4; ++j) acc[i][j] = 0ull;

        #pragma unroll 8
        for (int c = 0; c < 128; ++c) {
            float4 z = zp[c * 16 + vg];                       // half-warp broadcast
            ulonglong2 qa = cbu[c * 32 + cg];                 // codes 4cg..4cg+3
            ulonglong2 qb = cbu[c * 32 + cg + 16];            // codes 64+4cg..64+4cg+3
            unsigned long long zz0 = splat2(z.x);
            unsigned long long zz1 = splat2(z.y);
            unsigned long long zz2 = splat2(z.z);
            unsigned long long zz3 = splat2(z.w);
            acc[0][0] = ffma2(zz0, qa.x, acc[0][0]);
            acc[0][1] = ffma2(zz0, qa.y, acc[0][1]);
            acc[0][2] = ffma2(zz0, qb.x, acc[0][2]);
            acc[0][3] = ffma2(zz0, qb.y, acc[0][3]);
            acc[1][0] = ffma2(zz1, qa.x, acc[1][0]);
            acc[1][1] = ffma2(zz1, qa.y, acc[1][1]);
            acc[1][2] = ffma2(zz1, qb.x, acc[1][2]);
            acc[1][3] = ffma2(zz1, qb.y, acc[1][3]);
            acc[2][0] = ffma2(zz2, qa.x, acc[2][0]);
            acc[2][1] = ffma2(zz2, qa.y, acc[2][1]);
            acc[2][2] = ffma2(zz2, qb.x, acc[2][2]);
            acc[2][3] = ffma2(zz2, qb.y, acc[2][3]);
            acc[3][0] = ffma2(zz3, qa.x, acc[3][0]);
            acc[3][1] = ffma2(zz3, qa.y, acc[3][1]);
            acc[3][2] = ffma2(zz3, qb.x, acc[3][2]);
            acc[3][3] = ffma2(zz3, qb.y, acc[3][3]);
        }

        // ---- epilogue: e = c2 - rn2*dot, running argmin (ascending code order) ----
        float cv[8];
        int   base0 = cg * 4, base1 = (cg + 16) * 4;
        #pragma unroll
        for (int t = 0; t < 4; ++t) {
            cv[t]     = sf[OFF_C2 + kt * 128 + base0 + t];
            cv[4 + t] = sf[OFF_C2 + kt * 128 + base1 + t];
        }
        #pragma unroll
        for (int i = 0; i < 4; ++i) {
            float r2 = sf[OFF_RN2 + vg * 4 + i];
            #pragma unroll
            for (int j = 0; j < 4; ++j) {
                float lo, hi;
                unpack2(acc[i][j], lo, hi);
                int cb = (j < 2) ? (base0 + (j & 1) * 2) : (base1 + (j & 1) * 2);
                float e0 = fmaf(-r2, lo, cv[(j >> 1) * 4 + (j & 1) * 2 + 0]);
                float e1 = fmaf(-r2, hi, cv[(j >> 1) * 4 + (j & 1) * 2 + 1]);
                int code = kt * 128 + cb;
                if (e0 < bestE[i]) { bestE[i] = e0; bestI[i] = code; }
                if (e1 < bestE[i]) { bestE[i] = e1; bestI[i] = code + 1; }
            }
        }
        __syncthreads();   // done reading this buffer before it is refilled
    }

    // ---- argmin reduce across the 16 code-group lanes (tie -> smallest index) ----
    #pragma unroll
    for (int i = 0; i < 4; ++i) {
        float e  = bestE[i];
        int   id = bestI[i];
        #pragma unroll
        for (int off = 8; off > 0; off >>= 1) {
            float oe = __shfl_down_sync(0xffffffffu, e,  off, 16);
            int   oi = __shfl_down_sync(0xffffffffu, id, off, 16);
            if (oe < e || (oe == e && oi < id)) { e = oe; id = oi; }
        }
        if (cg == 0) {
            int v = vg * 4 + i;
            reinterpret_cast<int*>(sf + OFF_SIDX)[v] = id;
            bestE[i] = sqrtf(fmaxf(sf[OFF_Z2 + v] + e, 0.f));   // ||z - q||
        }
    }
    if (cg == 0)
        sf[OFF_RED + vg] = (bestE[0] + bestE[1]) + (bestE[2] + bestE[3]);
    __syncthreads();
    if (tid == 0) {
        float s = 0.f;
        #pragma unroll
        for (int i = 0; i < 16; ++i) s += sf[OFF_RED + i];
        g_partial[blockIdx.x] = s;
    }

    // ---- gather chosen rows into SMEM (coalesced L2 reads), coalesced store ----
    float* qr = sf + OFF_BUF0;   // [64][129]
    {
        int wrp = tid >> 5, lane = tid & 31;
        const int* sidx = reinterpret_cast<const int*>(sf + OFF_SIDX);
        #pragma unroll
        for (int vv = 0; vv < 8; ++vv) {
            int v   = wrp * 8 + vv;
            int row = sidx[v];
            const float* cr = codebook + row * CH;
            #pragma unroll
            for (int cc = 0; cc < 4; ++cc) {
                int c = cc * 32 + lane;
                qr[v * 129 + c] = cr[c];
            }
        }
    }
    __syncthreads();
    {
        float* obase = out + (size_t)b * (CH * 4096) + h * 64;
        const int w  = tid & 63;
        const int c0 = tid >> 6;
        #pragma unroll
        for (int it = 0; it < 32; ++it) {
            int c = it * 4 + c0;
            obase[c * 4096 + w] = qr[w * 129 + c];
        }
    }
}

// ---------------------------------------------------------------------------
__global__ void finalize_kernel(float* __restrict__ out) {
    __shared__ float s[256];
    int t = threadIdx.x;
    float a = 0.f;
    #pragma unroll
    for (int i = 0; i < 4; ++i) a += g_partial[t + i * 256];
    s[t] = a;
    __syncthreads();
    for (int off = 128; off > 0; off >>= 1) {
        if (t < off) s[t] += s[t + off];
        __syncthreads();
    }
    if (t == 0) {
        float mean = s[0] * (1.0f / 65536.0f);
        out[QELEMS]     = 0.25f * mean;   // loss0
        out[QELEMS + 1] = mean;           // loss1
    }
}

extern "C" void kernel_launch(void* const* d_in, const int* in_sizes, int n_in,
                              void* d_out, int out_size) {
    const float* x        = (const float*)d_in[0];
    const float* codebook = (const float*)d_in[1];
    float*       out      = (float*)d_out;

    prep_kernel<<<CB_K, CH>>>(codebook);

    cudaFuncSetAttribute(vq_main, cudaFuncAttributeMaxDynamicSharedMemorySize,
                         SMEM_FLOATS * 4);
    vq_main<<<NBLK, 256, SMEM_FLOATS * 4>>>(x, codebook, out);

    if (out_size >= QELEMS + 2)
        finalize_kernel<<<1, 256>>>(out);
}

// round 5
// speedup vs baseline: 1.3743x; 1.3743x over previous
#include <cuda_runtime.h>
#include <cuda_bf16.h>
#include <math.h>
#include <stdint.h>

#define CB_K   1024
#define CH     128
#define QELEMS 8388608

__device__ float g_c2[CB_K];
__device__ int   g_maxc2bits = 0;
__device__ float g_partial[1024];
__device__ unsigned short g_cbbf[CB_K * 136];             // bf16 codebook, row stride 136
__device__ unsigned short g_dots[(size_t)65536 * 1024];   // bf16 dots, 128MB

// ---------------- helpers ----------------
__device__ __forceinline__ uint32_t smem_u32(const void* p) {
    uint32_t a;
    asm("{ .reg .u64 t; cvta.to.shared.u64 t, %1; cvt.u32.u64 %0, t; }" : "=r"(a) : "l"(p));
    return a;
}
__device__ __forceinline__ void cp_async16(uint32_t d, const void* s) {
    asm volatile("cp.async.cg.shared.global [%0], [%1], 16;" :: "r"(d), "l"(s));
}
#define CP_COMMIT() asm volatile("cp.async.commit_group;")
__device__ __forceinline__ uint32_t packbf(float lo, float hi) {
    uint32_t d;
    asm("cvt.rn.bf16x2.f32 %0, %1, %2;" : "=r"(d) : "f"(hi), "f"(lo));
    return d;
}
#define LDSM4(rr, addr)                                                         \
    asm volatile("ldmatrix.sync.aligned.m8n8.x4.shared.b16 {%0,%1,%2,%3}, [%4];" \
        : "=r"((rr)[0]),"=r"((rr)[1]),"=r"((rr)[2]),"=r"((rr)[3]) : "r"(addr))
#define MMA(dd, aa, b0, b1)                                                     \
    asm volatile("mma.sync.aligned.m16n8k16.row.col.f32.bf16.bf16.f32 "         \
        "{%0,%1,%2,%3}, {%4,%5,%6,%7}, {%8,%9}, {%0,%1,%2,%3};"                 \
        : "+f"((dd)[0]),"+f"((dd)[1]),"+f"((dd)[2]),"+f"((dd)[3])               \
        : "r"((aa)[0]),"r"((aa)[1]),"r"((aa)[2]),"r"((aa)[3]), "r"(b0),"r"(b1))

// ---------------------------------------------------------------------------
__global__ void prep_kernel(const float* __restrict__ codebook) {
    int k = blockIdx.x, c = threadIdx.x;
    float v = codebook[k * CH + c];
    __nv_bfloat16 h = __float2bfloat16(v);
    g_cbbf[k * 136 + c] = *reinterpret_cast<unsigned short*>(&h);
    float s = v * v;
    #pragma unroll
    for (int o = 16; o > 0; o >>= 1) s += __shfl_down_sync(0xffffffffu, s, o);
    __shared__ float ws[4];
    if ((c & 31) == 0) ws[c >> 5] = s;
    __syncthreads();
    if (c == 0) {
        float c2 = (ws[0] + ws[1]) + (ws[2] + ws[3]);
        g_c2[k] = c2;
        atomicMax(&g_maxc2bits, __float_as_int(c2));
    }
}

// ---------------------------------------------------------------------------
// gemm: SMEM bytes: STG(zbf/dots staging)@0 (34816), CB0@34816, CB1@69632,
//       rinv@104448 (512B). zsT fp32 overlays CB0/CB1 during prologue.
// ---------------------------------------------------------------------------
#define G_STG   0u
#define G_CB0   34816u
#define G_CB1   69632u
#define G_RINV  104448u
#define GEMM_SMEM 104960

__device__ __forceinline__ void issue_tile(uint32_t dst, int j, int tid) {
    const unsigned char* src = reinterpret_cast<const unsigned char*>(g_cbbf)
                               + (size_t)j * 34816;
    #pragma unroll
    for (int it = 0; it < 9; ++it) {
        int idx = it * 256 + tid;
        if (idx < 2176) cp_async16(dst + idx * 16, src + idx * 16);
    }
}

__global__ void __launch_bounds__(256, 2) gemm_kernel(const float* __restrict__ x) {
    extern __shared__ unsigned char sm[];
    const uint32_t sb = smem_u32(sm);
    const int tid = threadIdx.x, w = tid >> 5, lane = tid & 31;
    const int t = blockIdx.x;

    float* zst  = reinterpret_cast<float*>(sm + G_CB0);
    float* rinv = reinterpret_cast<float*>(sm + G_RINV);

    // x tile -> zst[c][m] (coalesced)
    const float* xb = x + (size_t)(t >> 5) * 524288 + (t & 31) * 128;
    #pragma unroll 8
    for (int it = 0; it < 64; ++it) {
        int idx = it * 256 + tid;
        zst[idx] = xb[(idx >> 7) * 4096 + (idx & 127)];
    }
    __syncthreads();
    if (tid < 128) {
        float s0 = 0.f, s1 = 0.f, s2 = 0.f, s3 = 0.f;
        #pragma unroll
        for (int c = 0; c < 128; c += 4) {
            float v0 = zst[(c+0)*128 + tid], v1 = zst[(c+1)*128 + tid];
            float v2 = zst[(c+2)*128 + tid], v3 = zst[(c+3)*128 + tid];
            s0 = fmaf(v0, v0, s0); s1 = fmaf(v1, v1, s1);
            s2 = fmaf(v2, v2, s2); s3 = fmaf(v3, v3, s3);
        }
        rinv[tid] = 1.0f / fmaxf(sqrtf((s0 + s1) + (s2 + s3)), 1e-12f);
    }
    __syncthreads();
    // build bf16 A image zbf[m][k], stride 136 u16 (in STG region)
    {
        int m = tid >> 1, hf = tid & 1;
        float r = rinv[m];
        uint32_t* dst = reinterpret_cast<uint32_t*>(sm + G_STG + m * 272 + hf * 128);
        #pragma unroll
        for (int i = 0; i < 32; ++i) {
            int c = hf * 64 + 2 * i;
            dst[i] = packbf(zst[c * 128 + m] * r, zst[(c + 1) * 128 + m] * r);
        }
    }
    __syncthreads();
    // A fragments into registers (rows 16w..16w+15, all K)
    uint32_t a[8][4];
    #pragma unroll
    for (int kk = 0; kk < 8; ++kk) {
        uint32_t ad = sb + G_STG + (16 * w + (lane & 15)) * 272
                    + (kk * 16 + (lane >> 4) * 8) * 2;
        LDSM4(a[kk], ad);
    }
    __syncthreads();   // zst & zbf now dead

    issue_tile(sb + G_CB0, 0, tid);
    CP_COMMIT();

    for (int j = 0; j < 8; ++j) {
        if (j < 7) {
            issue_tile(sb + (((j + 1) & 1) ? G_CB1 : G_CB0), j + 1, tid);
            CP_COMMIT();
            asm volatile("cp.async.wait_group 1;" ::: "memory");
        } else {
            asm volatile("cp.async.wait_group 0;" ::: "memory");
        }
        __syncthreads();
        const uint32_t cb = sb + ((j & 1) ? G_CB1 : G_CB0);

        float d[16][4];
        #pragma unroll
        for (int f = 0; f < 16; ++f)
            #pragma unroll
            for (int i = 0; i < 4; ++i) d[f][i] = 0.f;

        #pragma unroll
        for (int kk = 0; kk < 8; ++kk) {
            #pragma unroll
            for (int g = 0; g < 8; ++g) {
                uint32_t b[4];
                uint32_t ba = cb + ((16 * g + (lane & 7) + ((lane >> 4) & 1) * 8) * 136
                            + kk * 16 + ((lane >> 3) & 1) * 8) * 2;
                LDSM4(b, ba);
                MMA(d[2 * g],     a[kk], b[0], b[1]);
                MMA(d[2 * g + 1], a[kk], b[2], b[3]);
            }
        }

        // stage dots bf16 (STG reused)
        #pragma unroll
        for (int g = 0; g < 8; ++g)
            #pragma unroll
            for (int hi = 0; hi < 2; ++hi) {
                int f = 2 * g + hi;
                int col = g * 16 + hi * 8 + 2 * (lane & 3);
                int r0 = 16 * w + (lane >> 2);
                *reinterpret_cast<uint32_t*>(sm + G_STG + r0 * 272 + col * 2) =
                    packbf(d[f][0], d[f][1]);
                *reinterpret_cast<uint32_t*>(sm + G_STG + (r0 + 8) * 272 + col * 2) =
                    packbf(d[f][2], d[f][3]);
            }
        __syncthreads();
        // coalesced copy to g_dots
        {
            unsigned char* gbase = reinterpret_cast<unsigned char*>(g_dots)
                                 + (size_t)t * 128 * 2048 + j * 256;
            #pragma unroll
            for (int it = 0; it < 8; ++it) {
                int cid = it * 256 + tid;          // 0..2047
                int row = cid >> 4, part = cid & 15;
                uint4 v = *reinterpret_cast<const uint4*>(sm + G_STG + row * 272 + part * 16);
                *reinterpret_cast<uint4*>(gbase + (size_t)row * 2048 + part * 16) = v;
            }
        }
        __syncthreads();
    }
}

// ---------------------------------------------------------------------------
// scan: word offsets in SMEM (dots tile 64x512 b32 padded to 513)
// ---------------------------------------------------------------------------
#define W_ZST  32832
#define W_C2   41024
#define W_RN2  42048
#define W_Z2   42112
#define W_PM   42176
#define W_PE   42432
#define W_PIX  42688
#define W_LS   42944
#define W_SIDX 43008
#define SCAN_SMEM (43072 * 4)

__global__ void __launch_bounds__(256, 1)
scan_kernel(const float* __restrict__ x, const float* __restrict__ codebook,
            float* __restrict__ out) {
    extern __shared__ uint32_t su[];
    float* sf = reinterpret_cast<float*>(su);
    int*   si = reinterpret_cast<int*>(su);
    const int tid = threadIdx.x;
    const int n0 = blockIdx.x * 64;
    const int b = n0 >> 12, h = (n0 >> 6) & 63;

    const uint32_t* gd = reinterpret_cast<const uint32_t*>(g_dots) + (size_t)n0 * 512;
    #pragma unroll 8
    for (int it = 0; it < 128; ++it) {
        int idx = it * 256 + tid;
        su[(idx >> 9) * 513 + (idx & 511)] = gd[idx];
    }
    const float* xbase = x + (size_t)b * (CH * 4096) + h * 64;
    {
        const int ww = tid & 63, c0 = tid >> 6;
        #pragma unroll
        for (int it = 0; it < 32; ++it) {
            int c = it * 4 + c0;
            sf[W_ZST + c * 64 + ww] = xbase[c * 4096 + ww];
        }
    }
    #pragma unroll
    for (int i = 0; i < 4; ++i) sf[W_C2 + i * 256 + tid] = g_c2[i * 256 + tid];
    __syncthreads();

    if (tid < 64) {
        float s0 = 0.f, s1 = 0.f, s2 = 0.f, s3 = 0.f;
        #pragma unroll
        for (int c = 0; c < 128; c += 4) {
            float v0 = sf[W_ZST + (c+0)*64 + tid], v1 = sf[W_ZST + (c+1)*64 + tid];
            float v2 = sf[W_ZST + (c+2)*64 + tid], v3 = sf[W_ZST + (c+3)*64 + tid];
            s0 = fmaf(v0, v0, s0); s1 = fmaf(v1, v1, s1);
            s2 = fmaf(v2, v2, s2); s3 = fmaf(v3, v3, s3);
        }
        float s = (s0 + s1) + (s2 + s3);
        float r = 1.0f / fmaxf(sqrtf(s), 1e-12f);
        sf[W_RN2 + tid] = 2.0f * r;
        sf[W_Z2  + tid] = s * r * r;
    }

    const int v = tid & 63, q = tid >> 6;
    {
        float mn = 3.4e38f;
        const uint32_t* dr = su + v * 513 + q * 128;
        #pragma unroll 4
        for (int ww = 0; ww < 128; ++ww) {
            uint32_t u = dr[ww];
            float f0 = __uint_as_float(u << 16);
            float f1 = __uint_as_float(u & 0xFFFF0000u);
            int k0 = q * 256 + 2 * ww;
            float e0 = fmaf(-2.f, f0, sf[W_C2 + k0]);
            float e1 = fmaf(-2.f, f1, sf[W_C2 + k0 + 1]);
            mn = fminf(mn, fminf(e0, e1));
        }
        sf[W_PM + q * 64 + v] = mn;
    }
    __syncthreads();
    if (tid < 64) {
        float m = sf[W_PM + tid];
        #pragma unroll
        for (int qq = 1; qq < 4; ++qq) m = fminf(m, sf[W_PM + qq * 64 + tid]);
        sf[W_PM + tid] = m;
    }
    __syncthreads();

    {
        float wnd = sqrtf(__int_as_float(g_maxc2bits)) * 0.06f;
        float T = sf[W_PM + v] + wnd;
        float r2 = sf[W_RN2 + v];
        float be = 3.4e38f; int bi = 0x7fffffff;
        const uint32_t* dr = su + v * 513 + q * 128;
        for (int ww = 0; ww < 128; ++ww) {
            uint32_t u = dr[ww];
            #pragma unroll
            for (int hb = 0; hb < 2; ++hb) {
                float f = hb ? __uint_as_float(u & 0xFFFF0000u)
                             : __uint_as_float(u << 16);
                int k = q * 256 + 2 * ww + hb;
                if (fmaf(-2.f, f, sf[W_C2 + k]) <= T) {
                    const float* cr = codebook + k * CH;
                    float d0 = 0.f, d1 = 0.f, d2 = 0.f, d3 = 0.f;
                    #pragma unroll
                    for (int c = 0; c < 128; c += 4) {
                        d0 = fmaf(sf[W_ZST + (c+0)*64 + v], cr[c+0], d0);
                        d1 = fmaf(sf[W_ZST + (c+1)*64 + v], cr[c+1], d1);
                        d2 = fmaf(sf[W_ZST + (c+2)*64 + v], cr[c+2], d2);
                        d3 = fmaf(sf[W_ZST + (c+3)*64 + v], cr[c+3], d3);
                    }
                    float ef = fmaf(-r2, (d0 + d1) + (d2 + d3), sf[W_C2 + k]);
                    if (ef < be) { be = ef; bi = k; }
                }
            }
        }
        sf[W_PE + q * 64 + v] = be;
        si[W_PIX + q * 64 + v] = bi;
    }
    __syncthreads();
    if (tid < 64) {
        float be = sf[W_PE + tid]; int bi = si[W_PIX + tid];
        #pragma unroll
        for (int qq = 1; qq < 4; ++qq) {
            float e2 = sf[W_PE + qq * 64 + tid];
            int   i2 = si[W_PIX + qq * 64 + tid];
            if (e2 < be || (e2 == be && i2 < bi)) { be = e2; bi = i2; }
        }
        si[W_SIDX + tid] = bi;
        sf[W_LS + tid] = sqrtf(fmaxf(sf[W_Z2 + tid] + be, 0.f));
    }
    __syncthreads();
    if (tid == 0) {
        float s = 0.f;
        #pragma unroll
        for (int i = 0; i < 64; ++i) s += sf[W_LS + i];
        g_partial[blockIdx.x] = s;
    }
    __syncthreads();

    // q gather (coalesced codebook reads) + coalesced store
    float* qr = sf;
    {
        int wrp = tid >> 5, lane = tid & 31;
        #pragma unroll
        for (int vv = 0; vv < 8; ++vv) {
            int vx = wrp * 8 + vv;
            const float* cr = codebook + si[W_SIDX + vx] * CH;
            #pragma unroll
            for (int cc = 0; cc < 4; ++cc) {
                int c = cc * 32 + lane;
                qr[vx * 129 + c] = cr[c];
            }
        }
    }
    __syncthreads();
    {
        float* obase = out + (size_t)b * (CH * 4096) + h * 64;
        const int ww = tid & 63, c0 = tid >> 6;
        #pragma unroll
        for (int it = 0; it < 32; ++it) {
            int c = it * 4 + c0;
            obase[c * 4096 + ww] = qr[ww * 129 + c];
        }
    }
}

// ---------------------------------------------------------------------------
__global__ void finalize_kernel(float* __restrict__ out) {
    __shared__ float s[256];
    int t = threadIdx.x;
    float a = 0.f;
    #pragma unroll
    for (int i = 0; i < 4; ++i) a += g_partial[t + i * 256];
    s[t] = a;
    __syncthreads();
    for (int off = 128; off > 0; off >>= 1) {
        if (t < off) s[t] += s[t + off];
        __syncthreads();
    }
    if (t == 0) {
        float mean = s[0] * (1.0f / 65536.0f);
        out[QELEMS]     = 0.25f * mean;
        out[QELEMS + 1] = mean;
    }
}

extern "C" void kernel_launch(void* const* d_in, const int* in_sizes, int n_in,
                              void* d_out, int out_size) {
    const float* x        = (const float*)d_in[0];
    const float* codebook = (const float*)d_in[1];
    float*       out      = (float*)d_out;

    prep_kernel<<<CB_K, CH>>>(codebook);

    cudaFuncSetAttribute(gemm_kernel, cudaFuncAttributeMaxDynamicSharedMemorySize, GEMM_SMEM);
    gemm_kernel<<<512, 256, GEMM_SMEM>>>(x);

    cudaFuncSetAttribute(scan_kernel, cudaFuncAttributeMaxDynamicSharedMemorySize, SCAN_SMEM);
    scan_kernel<<<1024, 256, SCAN_SMEM>>>(x, codebook, out);

    if (out_size >= QELEMS + 2)
        finalize_kernel<<<1, 256>>>(out);
}

// round 6
// speedup vs baseline: 2.1081x; 1.5339x over previous
#include <cuda_runtime.h>
#include <cuda_bf16.h>
#include <math.h>
#include <stdint.h>

#define CB_K   1024
#define CH     128
#define QELEMS 8388608

__device__ float g_c2[CB_K];
__device__ int   g_maxc2bits = 0;
__device__ float g_partial[1024];
__device__ unsigned short g_cbbf[CB_K * 136];   // bf16 codebook, row stride 136 u16

// ---------------- helpers ----------------
__device__ __forceinline__ uint32_t smem_u32(const void* p) {
    uint32_t a;
    asm("{ .reg .u64 t; cvta.to.shared.u64 t, %1; cvt.u32.u64 %0, t; }" : "=r"(a) : "l"(p));
    return a;
}
__device__ __forceinline__ void cp_async16(uint32_t d, const void* s) {
    asm volatile("cp.async.cg.shared.global [%0], [%1], 16;" :: "r"(d), "l"(s));
}
#define CP_COMMIT() asm volatile("cp.async.commit_group;")
__device__ __forceinline__ uint32_t packbf(float lo, float hi) {
    uint32_t d;
    asm("cvt.rn.bf16x2.f32 %0, %1, %2;" : "=r"(d) : "f"(hi), "f"(lo));
    return d;
}
#define LDSM4(rr, addr)                                                          \
    asm volatile("ldmatrix.sync.aligned.m8n8.x4.shared.b16 {%0,%1,%2,%3}, [%4];" \
        : "=r"((rr)[0]),"=r"((rr)[1]),"=r"((rr)[2]),"=r"((rr)[3]) : "r"(addr))
#define MMA(dd, aa, b0, b1)                                                      \
    asm volatile("mma.sync.aligned.m16n8k16.row.col.f32.bf16.bf16.f32 "          \
        "{%0,%1,%2,%3}, {%4,%5,%6,%7}, {%8,%9}, {%0,%1,%2,%3};"                  \
        : "+f"((dd)[0]),"+f"((dd)[1]),"+f"((dd)[2]),"+f"((dd)[3])                \
        : "r"((aa)[0]),"r"((aa)[1]),"r"((aa)[2]),"r"((aa)[3]), "r"(b0),"r"(b1))

// ---------------------------------------------------------------------------
__global__ void prep_kernel(const float* __restrict__ codebook) {
    int k = blockIdx.x, c = threadIdx.x;
    float v = codebook[k * CH + c];
    __nv_bfloat16 hh = __float2bfloat16(v);
    g_cbbf[k * 136 + c] = *reinterpret_cast<unsigned short*>(&hh);
    float s = v * v;
    #pragma unroll
    for (int o = 16; o > 0; o >>= 1) s += __shfl_down_sync(0xffffffffu, s, o);
    __shared__ float ws[4];
    if ((c & 31) == 0) ws[c >> 5] = s;
    __syncthreads();
    if (c == 0) {
        float c2 = (ws[0] + ws[1]) + (ws[2] + ws[3]);
        g_c2[k] = c2;
        atomicMax(&g_maxc2bits, __float_as_int(c2));
    }
}

// ---------------------------------------------------------------------------
// Fused kernel. SMEM word offsets:
//   W_E    = 0      : e32[64 rows][513 u32]  (offset-bf16 e pairs); first 4352
//                     words double as the bf16 A image during the prologue
//   W_ZST  = 32832  : raw x fp32 [c][v] 128x64
//   W_CB0  = 41024  : B tile 0 (64 codes x 136 u16)
//   W_CB1  = 45376  : B tile 1
//   W_C2   = 49728  : c2[1024]
//   W_RN2  = 50752, W_Z2 = 50816, W_RINV = 50880,
//   W_PM   = 50944, W_PE = 51200, W_PIX = 51456, W_LS = 51712, W_SIDX = 51776
// ---------------------------------------------------------------------------
#define W_E    0
#define W_ZST  32832
#define W_CB0  41024
#define W_CB1  45376
#define W_C2   49728
#define W_RN2  50752
#define W_Z2   50816
#define W_RINV 50880
#define W_PM   50944
#define W_PE   51200
#define W_PIX  51456
#define W_LS   51712
#define W_SIDX 51776
#define SMEM_WORDS 51840
#define SMEM_BYTES (SMEM_WORDS * 4)

__device__ __forceinline__ void issue_tile(uint32_t dstb, int j, int tid) {
    const unsigned char* src = reinterpret_cast<const unsigned char*>(g_cbbf)
                               + (size_t)j * 17408;
    #pragma unroll
    for (int it = 0; it < 5; ++it) {
        int idx = it * 256 + tid;
        if (idx < 1088) cp_async16(dstb + idx * 16, src + idx * 16);
    }
    CP_COMMIT();
}

__global__ void __launch_bounds__(256, 1)
vq_fused(const float* __restrict__ x, const float* __restrict__ codebook,
         float* __restrict__ out) {
    extern __shared__ uint32_t su[];
    float* sf = reinterpret_cast<float*>(su);
    int*   si = reinterpret_cast<int*>(su);
    const uint32_t sb = smem_u32(su);
    const int tid = threadIdx.x, w = tid >> 5, lane = tid & 31;
    const int wp = w >> 1, chh = w & 1;       // row-quad / col-half
    const int n0 = blockIdx.x * 64;
    const int b = n0 >> 12, h = (n0 >> 6) & 63;

    // prefetch B tiles 0,1 immediately (overlap with x load)
    issue_tile(sb + W_CB0 * 4, 0, tid);
    issue_tile(sb + W_CB1 * 4, 1, tid);

    // raw x tile -> zsT[c][v] (coalesced along w)
    const float* xbase = x + (size_t)b * (CH * 4096) + h * 64;
    {
        const int ww = tid & 63, c0 = tid >> 6;
        #pragma unroll
        for (int it = 0; it < 32; ++it) {
            int c = it * 4 + c0;
            sf[W_ZST + c * 64 + ww] = xbase[c * 4096 + ww];
        }
    }
    #pragma unroll
    for (int i = 0; i < 4; ++i) sf[W_C2 + i * 256 + tid] = g_c2[i * 256 + tid];
    __syncthreads();

    // per-vector norms
    if (tid < 64) {
        float s0 = 0.f, s1 = 0.f, s2 = 0.f, s3 = 0.f;
        #pragma unroll
        for (int c = 0; c < 128; c += 4) {
            float v0 = sf[W_ZST + (c+0)*64 + tid], v1 = sf[W_ZST + (c+1)*64 + tid];
            float v2 = sf[W_ZST + (c+2)*64 + tid], v3 = sf[W_ZST + (c+3)*64 + tid];
            s0 = fmaf(v0, v0, s0); s1 = fmaf(v1, v1, s1);
            s2 = fmaf(v2, v2, s2); s3 = fmaf(v3, v3, s3);
        }
        float s = (s0 + s1) + (s2 + s3);
        float r = 1.0f / fmaxf(sqrtf(s), 1e-12f);
        sf[W_RINV + tid] = r;
        sf[W_RN2  + tid] = 2.0f * r;
        sf[W_Z2   + tid] = s * r * r;
    }
    __syncthreads();

    // bf16 A image (normalized z), rows x 136-u16 stride, in W_E overlay
    {
        int m = tid >> 2, qq = tid & 3;
        float r = sf[W_RINV + m];
        uint32_t* dst = su + (m * 272 + qq * 64) / 4;
        #pragma unroll
        for (int i = 0; i < 16; ++i) {
            int c = qq * 32 + 2 * i;
            dst[i] = packbf(sf[W_ZST + c * 64 + m] * r,
                            sf[W_ZST + (c + 1) * 64 + m] * r);
        }
    }
    __syncthreads();

    // A fragments: rows 16*wp..+15, all K
    uint32_t a[8][4];
    #pragma unroll
    for (int kk = 0; kk < 8; ++kk) {
        uint32_t ad = sb + (16 * wp + (lane & 15)) * 272 + (kk * 16 + (lane >> 4) * 8) * 2;
        LDSM4(a[kk], ad);
    }
    __syncthreads();   // A image region now reusable as e storage

    const float OFF = 0.75f * __int_as_float(g_maxc2bits);

    for (int j = 0; j < 16; ++j) {
        asm volatile("cp.async.wait_group 1;" ::: "memory");
        if (j == 15) asm volatile("cp.async.wait_group 0;" ::: "memory");
        __syncthreads();
        const uint32_t cb = sb + ((j & 1) ? W_CB1 : W_CB0) * 4;

        float d[4][4];
        #pragma unroll
        for (int f = 0; f < 4; ++f)
            #pragma unroll
            for (int i = 0; i < 4; ++i) d[f][i] = 0.f;

        #pragma unroll
        for (int kk = 0; kk < 8; ++kk) {
            #pragma unroll
            for (int gg = 0; gg < 2; ++gg) {
                uint32_t bfr[4];
                uint32_t ba = cb + ((chh * 32 + gg * 16 + (lane & 7) + ((lane >> 4) & 1) * 8) * 136
                            + kk * 16 + ((lane >> 3) & 1) * 8) * 2;
                LDSM4(bfr, ba);
                MMA(d[2 * gg],     a[kk], bfr[0], bfr[1]);
                MMA(d[2 * gg + 1], a[kk], bfr[2], bfr[3]);
            }
        }

        // epilogue: eoff = c2 - 2*dot - OFF, packed bf16 pairs into e32
        int r0 = 16 * wp + (lane >> 2);
        #pragma unroll
        for (int gg = 0; gg < 2; ++gg)
            #pragma unroll
            for (int hi = 0; hi < 2; ++hi) {
                int f = 2 * gg + hi;
                int k0 = j * 64 + chh * 32 + gg * 16 + hi * 8 + 2 * (lane & 3);
                float cv0 = sf[W_C2 + k0]     - OFF;
                float cv1 = sf[W_C2 + k0 + 1] - OFF;
                su[W_E + r0 * 513 + (k0 >> 1)] =
                    packbf(fmaf(-2.f, d[f][0], cv0), fmaf(-2.f, d[f][1], cv1));
                su[W_E + (r0 + 8) * 513 + (k0 >> 1)] =
                    packbf(fmaf(-2.f, d[f][2], cv0), fmaf(-2.f, d[f][3], cv1));
            }
        __syncthreads();
        if (j + 2 < 16) issue_tile(sb + ((j & 1) ? W_CB1 : W_CB0) * 4, j + 2, tid);
    }

    // ---- phase 2: filter min over offset-bf16 e ----
    const int v = tid & 63, q = tid >> 6;
    {
        float mn = 3.4e38f;
        const uint32_t* dr = su + W_E + v * 513 + q * 128;
        #pragma unroll 4
        for (int ww = 0; ww < 128; ++ww) {
            uint32_t u = dr[ww];
            float f0 = __uint_as_float(u << 16);
            float f1 = __uint_as_float(u & 0xFFFF0000u);
            mn = fminf(mn, fminf(f0, f1));
        }
        sf[W_PM + q * 64 + v] = mn;
    }
    __syncthreads();
    if (tid < 64) {
        float m = sf[W_PM + tid];
        #pragma unroll
        for (int qq = 1; qq < 4; ++qq) m = fminf(m, sf[W_PM + qq * 64 + tid]);
        sf[W_PM + tid] = m;
    }
    __syncthreads();

    // ---- exact fp32 rescore of window candidates ----
    {
        float wnd = sqrtf(__int_as_float(g_maxc2bits)) * 0.06f;
        float T = sf[W_PM + v] + wnd;
        float r2 = sf[W_RN2 + v];
        float be = 3.4e38f; int bi = 0x7fffffff;
        const uint32_t* dr = su + W_E + v * 513 + q * 128;
        for (int ww = 0; ww < 128; ++ww) {
            uint32_t u = dr[ww];
            #pragma unroll
            for (int hb = 0; hb < 2; ++hb) {
                float f = hb ? __uint_as_float(u & 0xFFFF0000u)
                             : __uint_as_float(u << 16);
                if (f <= T) {
                    int k = q * 256 + 2 * ww + hb;
                    const float* cr = codebook + k * CH;
                    float d0 = 0.f, d1 = 0.f, d2 = 0.f, d3 = 0.f;
                    #pragma unroll
                    for (int c = 0; c < 128; c += 4) {
                        d0 = fmaf(sf[W_ZST + (c+0)*64 + v], cr[c+0], d0);
                        d1 = fmaf(sf[W_ZST + (c+1)*64 + v], cr[c+1], d1);
                        d2 = fmaf(sf[W_ZST + (c+2)*64 + v], cr[c+2], d2);
                        d3 = fmaf(sf[W_ZST + (c+3)*64 + v], cr[c+3], d3);
                    }
                    float ef = fmaf(-r2, (d0 + d1) + (d2 + d3), sf[W_C2 + k]);
                    if (ef < be) { be = ef; bi = k; }   // ascending k: ties -> smaller
                }
            }
        }
        sf[W_PE + q * 64 + v] = be;
        si[W_PIX + q * 64 + v] = bi;
    }
    __syncthreads();
    if (tid < 64) {
        float be = sf[W_PE + tid]; int bi = si[W_PIX + tid];
        #pragma unroll
        for (int qq = 1; qq < 4; ++qq) {
            float e2 = sf[W_PE + qq * 64 + tid];
            int   i2 = si[W_PIX + qq * 64 + tid];
            if (e2 < be || (e2 == be && i2 < bi)) { be = e2; bi = i2; }
        }
        si[W_SIDX + tid] = bi;
        sf[W_LS + tid] = sqrtf(fmaxf(sf[W_Z2 + tid] + be, 0.f));
    }
    __syncthreads();
    if (tid == 0) {
        float s = 0.f;
        #pragma unroll
        for (int i = 0; i < 64; ++i) s += sf[W_LS + i];
        g_partial[blockIdx.x] = s;
    }
    __syncthreads();

    // ---- q gather (coalesced codebook reads) + coalesced store ----
    float* qr = sf + W_E;   // [64][129]
    {
        int wrp = tid >> 5, ln = tid & 31;
        #pragma unroll
        for (int vv = 0; vv < 8; ++vv) {
            int vx = wrp * 8 + vv;
            const float* cr = codebook + si[W_SIDX + vx] * CH;
            #pragma unroll
            for (int cc = 0; cc < 4; ++cc) {
                int c = cc * 32 + ln;
                qr[vx * 129 + c] = cr[c];
            }
        }
    }
    __syncthreads();
    {
        float* obase = out + (size_t)b * (CH * 4096) + h * 64;
        const int ww = tid & 63, c0 = tid >> 6;
        #pragma unroll
        for (int it = 0; it < 32; ++it) {
            int c = it * 4 + c0;
            obase[c * 4096 + ww] = qr[ww * 129 + c];
        }
    }
}

// ---------------------------------------------------------------------------
__global__ void finalize_kernel(float* __restrict__ out) {
    __shared__ float s[256];
    int t = threadIdx.x;
    float a = 0.f;
    #pragma unroll
    for (int i = 0; i < 4; ++i) a += g_partial[t + i * 256];
    s[t] = a;
    __syncthreads();
    for (int off = 128; off > 0; off >>= 1) {
        if (t < off) s[t] += s[t + off];
        __syncthreads();
    }
    if (t == 0) {
        float mean = s[0] * (1.0f / 65536.0f);
        out[QELEMS]     = 0.25f * mean;
        out[QELEMS + 1] = mean;
    }
}

extern "C" void kernel_launch(void* const* d_in, const int* in_sizes, int n_in,
                              void* d_out, int out_size) {
    const float* x        = (const float*)d_in[0];
    const float* codebook = (const float*)d_in[1];
    float*       out      = (float*)d_out;

    prep_kernel<<<CB_K, CH>>>(codebook);

    cudaFuncSetAttribute(vq_fused, cudaFuncAttributeMaxDynamicSharedMemorySize, SMEM_BYTES);
    vq_fused<<<1024, 256, SMEM_BYTES>>>(x, codebook, out);

    if (out_size >= QELEMS + 2)
        finalize_kernel<<<1, 256>>>(out);
}